// round 3
// baseline (speedup 1.0000x reference)
#include <cuda_runtime.h>
#include <cstdint>

#define N_NODES_MAX 100000
#define DIM     64
#define MAX_SCAN_BLOCKS 256
#define CHUNK   64          // edges per pipeline chunk (64 * 256B = 16KB)
#define NPB     32          // dst nodes per block in gather kernel

// ---- scratch (allocation-free rule: __device__ globals) ----
__device__ __align__(256) float g_h[N_NODES_MAX * DIM];     // feature * norm_src
__device__ __align__(256) float g_accum[N_NODES_MAX * DIM]; // (segment_sum) * norm_dst
__device__ int g_count[N_NODES_MAX];                         // per-dst degree
__device__ int g_offset[N_NODES_MAX];                        // exclusive scan
__device__ int g_cursor[N_NODES_MAX];                        // fill cursors
__device__ int g_sorted_src[2000000];                        // src grouped by dst
__device__ int g_blocksums[MAX_SCAN_BLOCKS];

// ---------------- PTX helpers ----------------
__device__ __forceinline__ uint32_t smem_u32(const void* p) {
    uint32_t a;
    asm("{ .reg .u64 t; cvta.to.shared.u64 t, %1; cvt.u32.u64 %0, t; }"
        : "=r"(a) : "l"(p));
    return a;
}
#define MBAR_INIT(addr, cnt) \
    asm volatile("mbarrier.init.shared.b64 [%0], %1;" :: "r"(addr), "r"(cnt) : "memory")
#define MBAR_EXPECT_TX(addr, bytes) \
    asm volatile("mbarrier.arrive.expect_tx.shared.b64 _, [%0], %1;" \
                 :: "r"(addr), "r"(bytes) : "memory")
#define MBAR_ARRIVE(addr) \
    asm volatile("mbarrier.arrive.shared.b64 _, [%0];" :: "r"(addr) : "memory")
#define MBAR_WAIT(addr, ph) do {                                            \
    asm volatile(                                                           \
        "{\n\t.reg .pred P;\n\t"                                            \
        "W_%=:\n\t"                                                         \
        "mbarrier.try_wait.parity.acquire.cta.shared::cta.b64 P, [%0], %1, 0x989680;\n\t" \
        "@P bra.uni D_%=;\n\t"                                              \
        "bra.uni W_%=;\n\t"                                                 \
        "D_%=:\n\t}"                                                        \
        :: "r"(addr), "r"(ph) : "memory");                                  \
} while (0)
#define MBAR_WAIT_RELAXED(addr, ph) do {                                    \
    asm volatile(                                                           \
        "{\n\t.reg .pred P;\n\t"                                            \
        "W_%=:\n\t"                                                         \
        "mbarrier.try_wait.parity.relaxed.cta.shared::cta.b64 P, [%0], %1, 0x989680;\n\t" \
        "@P bra.uni D_%=;\n\t"                                              \
        "bra.uni W_%=;\n\t"                                                 \
        "D_%=:\n\t}"                                                        \
        :: "r"(addr), "r"(ph) : "memory");                                  \
} while (0)
#define BULK_CP_256(dst_smem, src_gmem, mbar) \
    asm volatile("cp.async.bulk.shared::cluster.global.mbarrier::complete_tx::bytes " \
                 "[%0], [%1], %2, [%3];" \
                 :: "r"(dst_smem), "l"(src_gmem), "r"(256u), "r"(mbar) : "memory")

// ---------------------------------------------------------------------------
// K1: h = feature * norm ; histogram of dst (g_count pre-zeroed by memset node)
// ---------------------------------------------------------------------------
__global__ void prep_hist_kernel(const float* __restrict__ feature,
                                 const float* __restrict__ norm,
                                 const int* __restrict__ dst,
                                 int n_vec4, int e) {
    int idx = blockIdx.x * blockDim.x + threadIdx.x;
    if (idx < n_vec4) {
        int node = idx >> 4;
        float nv = __ldg(norm + node);
        float4 f = reinterpret_cast<const float4*>(feature)[idx];
        f.x *= nv; f.y *= nv; f.z *= nv; f.w *= nv;
        reinterpret_cast<float4*>(g_h)[idx] = f;
    }
    if (idx < e) atomicAdd(&g_count[__ldg(dst + idx)], 1);
}

// ---------------------------------------------------------------------------
// K2a/b/c: exclusive prefix sum g_count -> g_offset (+ g_cursor)
// ---------------------------------------------------------------------------
__global__ void scan_block_kernel(int n) {
    __shared__ int sh[1024];
    int gid = blockIdx.x * 1024 + threadIdx.x;
    int v = (gid < n) ? g_count[gid] : 0;
    sh[threadIdx.x] = v;
    __syncthreads();
#pragma unroll
    for (int d = 1; d < 1024; d <<= 1) {
        int t = (threadIdx.x >= d) ? sh[threadIdx.x - d] : 0;
        __syncthreads();
        sh[threadIdx.x] += t;
        __syncthreads();
    }
    if (gid < n) g_offset[gid] = sh[threadIdx.x] - v;
    if (threadIdx.x == 1023) g_blocksums[blockIdx.x] = sh[1023];
}

__global__ void scan_sums_kernel(int nb) {
    __shared__ int sh[MAX_SCAN_BLOCKS];
    int v = (threadIdx.x < nb) ? g_blocksums[threadIdx.x] : 0;
    sh[threadIdx.x] = v;
    __syncthreads();
#pragma unroll
    for (int d = 1; d < MAX_SCAN_BLOCKS; d <<= 1) {
        int t = (threadIdx.x >= d) ? sh[threadIdx.x - d] : 0;
        __syncthreads();
        sh[threadIdx.x] += t;
        __syncthreads();
    }
    if (threadIdx.x < nb) g_blocksums[threadIdx.x] = sh[threadIdx.x] - v;
}

__global__ void scan_add_kernel(int n) {
    int gid = blockIdx.x * 1024 + threadIdx.x;
    if (gid < n) {
        int o = g_offset[gid] + g_blocksums[blockIdx.x];
        g_offset[gid] = o;
        g_cursor[gid] = o;
    }
}

// ---------------------------------------------------------------------------
// K3: bucket fill — src indices grouped by destination
// ---------------------------------------------------------------------------
__global__ void fill_kernel(const int* __restrict__ src,
                            const int* __restrict__ dst, int e) {
    int i = blockIdx.x * blockDim.x + threadIdx.x;
    if (i >= e) return;
    int d = __ldg(dst + i);
    int p = atomicAdd(&g_cursor[d], 1);
    g_sorted_src[p] = __ldg(src + i);
}

// ---------------------------------------------------------------------------
// K4: gather via bulk-copy pipeline.
// Block = 64 threads: warp 0 = producer (UBLKCP 256B row copies into a
// 2-stage smem ring), warp 1 = consumer (each lane owns 2 columns; LDS.64 +
// add.rn.f32x2 accumulate; one STG.64 row store per node).
// ---------------------------------------------------------------------------
__global__ void __launch_bounds__(64)
gather_kernel(const float* __restrict__ norm, int n, int e_total) {
    __shared__ __align__(128) char buf[2][CHUNK * 256];
    __shared__ __align__(8)  unsigned long long mbar[4]; // full0,full1,empty0,empty1

    int tid = threadIdx.x;
    uint32_t mb = smem_u32(mbar);
    uint32_t full_a[2]  = { mb,      mb + 8  };
    uint32_t empty_a[2] = { mb + 16, mb + 24 };
    uint32_t buf_a[2]   = { smem_u32(buf[0]), smem_u32(buf[1]) };

    if (tid == 0) {
        MBAR_INIT(full_a[0], 1);  MBAR_INIT(full_a[1], 1);
        MBAR_INIT(empty_a[0], 32); MBAR_INIT(empty_a[1], 32);
    }
    __syncthreads();

    int n0 = blockIdx.x * NPB;
    int n1 = min(n0 + NPB, n);
    if (n0 >= n) return;
    int e_base = g_offset[n0];
    int e_end  = (n1 < n) ? g_offset[n1] : e_total;
    int n_edges = e_end - e_base;

    if (tid < 32) {
        // ---- producer ----
        int lane = tid;
        int stage = 0, ph = 1;   // empty barriers: first wait passes immediately
        for (int base = 0; base < n_edges; base += CHUNK) {
            int cnt = min(CHUNK, n_edges - base);
            MBAR_WAIT_RELAXED(empty_a[stage], ph);
            __syncwarp();
            if (lane == 0) MBAR_EXPECT_TX(full_a[stage], (uint32_t)cnt * 256u);
            __syncwarp();
            for (int k = lane; k < cnt; k += 32) {
                int s = __ldg(g_sorted_src + e_base + base + k);
                const float* sp = g_h + (size_t)s * DIM;
                BULK_CP_256(buf_a[stage] + (uint32_t)k * 256u, sp, full_a[stage]);
            }
            stage ^= 1;
            if (stage == 0) ph ^= 1;
        }
    } else {
        // ---- consumer ----
        int lane = tid - 32;          // owns columns 2*lane, 2*lane+1
        int e_rel = 0, avail = 0, stage = 0, ph = 0;
        for (int node = n0; node < n1; node++) {
            int deg = __ldg(g_count + node);
            unsigned long long acc;
            asm("mov.b64 %0, {%1, %1};" : "=l"(acc) : "f"(0.0f));
            int k = 0;
            while (k < deg) {
                if (e_rel == avail) {
                    if (avail > 0) {
                        MBAR_ARRIVE(empty_a[stage]);
                        stage ^= 1;
                        if (stage == 0) ph ^= 1;
                    }
                    MBAR_WAIT(full_a[stage], ph);
                    avail += min(CHUNK, n_edges - avail);
                }
                int run = min(deg - k, avail - e_rel);
                uint32_t p = buf_a[stage] + (uint32_t)(e_rel & (CHUNK - 1)) * 256u
                             + (uint32_t)lane * 8u;
#pragma unroll 4
                for (int t = 0; t < run; t++) {
                    unsigned long long v;
                    asm volatile("ld.shared.b64 %0, [%1];" : "=l"(v) : "r"(p));
                    asm("add.rn.f32x2 %0, %0, %1;" : "+l"(acc) : "l"(v));
                    p += 256u;
                }
                k += run;
                e_rel += run;
            }
            float nv = __ldg(norm + node);
            unsigned long long nn;
            asm("mov.b64 %0, {%1, %1};" : "=l"(nn) : "f"(nv));
            asm("mul.rn.f32x2 %0, %0, %1;" : "+l"(acc) : "l"(nn));
            float r0, r1;
            asm("mov.b64 {%0, %1}, %2;" : "=f"(r0), "=f"(r1) : "l"(acc));
            reinterpret_cast<float2*>(g_accum + (size_t)node * DIM)[lane] =
                make_float2(r0, r1);
        }
    }
}

// ---------------------------------------------------------------------------
// K5: out = g_accum @ W^T + b   (f32x2 packed FMA, W transposed in shared)
// ---------------------------------------------------------------------------
__global__ void __launch_bounds__(256)
linear_kernel(const float* __restrict__ W,
              const float* __restrict__ b,
              float* __restrict__ out, int n) {
    __shared__ float Wt[DIM * DIM];
    __shared__ float bs[DIM];
    int tid = threadIdx.x;
    for (int k = tid; k < DIM * DIM; k += 256) {
        int j = k >> 6, i = k & 63;
        Wt[i * DIM + j] = W[k];
    }
    if (tid < DIM) bs[tid] = b[tid];
    __syncthreads();

    int node = blockIdx.x * 64 + (tid >> 2);
    int jg   = (tid & 3) * 16;
    if (node >= n) return;

    unsigned long long a01, a23, a45, a67;
    asm("mov.b64 %0, {%1, %2};" : "=l"(a01) : "f"(bs[jg + 0]), "f"(bs[jg + 1]));
    asm("mov.b64 %0, {%1, %2};" : "=l"(a23) : "f"(bs[jg + 2]), "f"(bs[jg + 3]));
    asm("mov.b64 %0, {%1, %2};" : "=l"(a45) : "f"(bs[jg + 4]), "f"(bs[jg + 5]));
    asm("mov.b64 %0, {%1, %2};" : "=l"(a67) : "f"(bs[jg + 6]), "f"(bs[jg + 7]));
    unsigned long long a89, aab, acd, aef;
    asm("mov.b64 %0, {%1, %2};" : "=l"(a89) : "f"(bs[jg + 8]), "f"(bs[jg + 9]));
    asm("mov.b64 %0, {%1, %2};" : "=l"(aab) : "f"(bs[jg + 10]), "f"(bs[jg + 11]));
    asm("mov.b64 %0, {%1, %2};" : "=l"(acd) : "f"(bs[jg + 12]), "f"(bs[jg + 13]));
    asm("mov.b64 %0, {%1, %2};" : "=l"(aef) : "f"(bs[jg + 14]), "f"(bs[jg + 15]));

    const float4* arow = reinterpret_cast<const float4*>(g_accum + (size_t)node * DIM);
#pragma unroll
    for (int i4 = 0; i4 < 16; i4++) {
        float4 a = arow[i4];
        const float av[4] = {a.x, a.y, a.z, a.w};
#pragma unroll
        for (int c = 0; c < 4; c++) {
            int i = i4 * 4 + c;
            unsigned long long aa;
            asm("mov.b64 %0, {%1, %1};" : "=l"(aa) : "f"(av[c]));
            const ulonglong2* wp = reinterpret_cast<const ulonglong2*>(&Wt[i * DIM + jg]);
            ulonglong2 w0 = wp[0], w1 = wp[1];
            asm("fma.rn.f32x2 %0, %1, %2, %0;" : "+l"(a01) : "l"(aa), "l"(w0.x));
            asm("fma.rn.f32x2 %0, %1, %2, %0;" : "+l"(a23) : "l"(aa), "l"(w0.y));
            asm("fma.rn.f32x2 %0, %1, %2, %0;" : "+l"(a45) : "l"(aa), "l"(w1.x));
            asm("fma.rn.f32x2 %0, %1, %2, %0;" : "+l"(a67) : "l"(aa), "l"(w1.y));
            const ulonglong2* wq = reinterpret_cast<const ulonglong2*>(&Wt[i * DIM + jg + 8]);
            ulonglong2 w2 = wq[0], w3 = wq[1];
            asm("fma.rn.f32x2 %0, %1, %2, %0;" : "+l"(a89) : "l"(aa), "l"(w2.x));
            asm("fma.rn.f32x2 %0, %1, %2, %0;" : "+l"(aab) : "l"(aa), "l"(w2.y));
            asm("fma.rn.f32x2 %0, %1, %2, %0;" : "+l"(acd) : "l"(aa), "l"(w3.x));
            asm("fma.rn.f32x2 %0, %1, %2, %0;" : "+l"(aef) : "l"(aa), "l"(w3.y));
        }
    }

    float r[16];
    asm("mov.b64 {%0, %1}, %2;" : "=f"(r[0]), "=f"(r[1]) : "l"(a01));
    asm("mov.b64 {%0, %1}, %2;" : "=f"(r[2]), "=f"(r[3]) : "l"(a23));
    asm("mov.b64 {%0, %1}, %2;" : "=f"(r[4]), "=f"(r[5]) : "l"(a45));
    asm("mov.b64 {%0, %1}, %2;" : "=f"(r[6]), "=f"(r[7]) : "l"(a67));
    asm("mov.b64 {%0, %1}, %2;" : "=f"(r[8]), "=f"(r[9]) : "l"(a89));
    asm("mov.b64 {%0, %1}, %2;" : "=f"(r[10]), "=f"(r[11]) : "l"(aab));
    asm("mov.b64 {%0, %1}, %2;" : "=f"(r[12]), "=f"(r[13]) : "l"(acd));
    asm("mov.b64 {%0, %1}, %2;" : "=f"(r[14]), "=f"(r[15]) : "l"(aef));
    float4* op = reinterpret_cast<float4*>(out + (size_t)node * DIM + jg);
#pragma unroll
    for (int q = 0; q < 4; q++)
        op[q] = make_float4(r[q * 4], r[q * 4 + 1], r[q * 4 + 2], r[q * 4 + 3]);
}

// ---------------------------------------------------------------------------
// Launch. Inputs: 0 feature [N,64] f32, 1 norm [N] f32, 2 src [E] i32,
//                 3 dst [E] i32, 4 W [64,64] f32, 5 b [64] f32. out [N,64] f32.
// ---------------------------------------------------------------------------
extern "C" void kernel_launch(void* const* d_in, const int* in_sizes, int n_in,
                              void* d_out, int out_size) {
    const float* feature = (const float*)d_in[0];
    const float* norm    = (const float*)d_in[1];
    const int*   src     = (const int*)d_in[2];
    const int*   dst     = (const int*)d_in[3];
    const float* W       = (const float*)d_in[4];
    const float* b       = (const float*)d_in[5];
    float*       out     = (float*)d_out;

    int n = in_sizes[1];
    int e = in_sizes[2];

    void* count_ptr = nullptr;
    cudaGetSymbolAddress(&count_ptr, g_count);
    cudaMemsetAsync(count_ptr, 0, (size_t)n * sizeof(int));

    int n_vec4 = n * 16;
    int work = max(n_vec4, e);
    prep_hist_kernel<<<(work + 255) / 256, 256>>>(feature, norm, dst, n_vec4, e);

    int nb = (n + 1023) / 1024;
    scan_block_kernel<<<nb, 1024>>>(n);
    scan_sums_kernel<<<1, MAX_SCAN_BLOCKS>>>(nb);
    scan_add_kernel<<<nb, 1024>>>(n);

    fill_kernel<<<(e + 511) / 512, 512>>>(src, dst, e);

    gather_kernel<<<(n + NPB - 1) / NPB, 64>>>(norm, n, e);

    linear_kernel<<<(n + 63) / 64, 256>>>(W, b, out, n);
}

// round 4
// speedup vs baseline: 1.2672x; 1.2672x over previous
#include <cuda_runtime.h>
#include <cstdint>

#define N_NODES_MAX 100000
#define DIM     64
#define MAX_SCAN_BLOCKS 256

// ---- scratch (allocation-free rule: __device__ globals) ----
__device__ __align__(256) float g_h[N_NODES_MAX * DIM];     // feature * norm_src
__device__ __align__(256) float g_accum[N_NODES_MAX * DIM]; // segment_sum * norm_dst
__device__ int g_count[N_NODES_MAX];      // per-dst degree
__device__ int g_offset[N_NODES_MAX];     // exclusive scan (PARTIAL, per 1024-tile)
__device__ int g_sorted_src[2000000];     // src indices grouped by dst
__device__ int g_blocksums[MAX_SCAN_BLOCKS]; // scanned tile sums

// ---------------------------------------------------------------------------
// K1: h = feature * norm ; histogram of dst (g_count pre-zeroed by memset)
// ---------------------------------------------------------------------------
__global__ void prep_hist_kernel(const float* __restrict__ feature,
                                 const float* __restrict__ norm,
                                 const int* __restrict__ dst,
                                 int n_vec4, int e) {
    int idx = blockIdx.x * blockDim.x + threadIdx.x;
    if (idx < n_vec4) {
        int node = idx >> 4;
        float nv = __ldg(norm + node);
        float4 f = reinterpret_cast<const float4*>(feature)[idx];
        f.x *= nv; f.y *= nv; f.z *= nv; f.w *= nv;
        reinterpret_cast<float4*>(g_h)[idx] = f;
    }
    if (idx < e) atomicAdd(&g_count[__ldg(dst + idx)], 1);
}

// ---------------------------------------------------------------------------
// K2a: per-1024-tile exclusive scan of counts -> g_offset (partial),
//      tile totals -> g_blocksums
// ---------------------------------------------------------------------------
__global__ void scan_block_kernel(int n) {
    __shared__ int sh[1024];
    int gid = blockIdx.x * 1024 + threadIdx.x;
    int v = (gid < n) ? g_count[gid] : 0;
    sh[threadIdx.x] = v;
    __syncthreads();
#pragma unroll
    for (int d = 1; d < 1024; d <<= 1) {
        int t = (threadIdx.x >= d) ? sh[threadIdx.x - d] : 0;
        __syncthreads();
        sh[threadIdx.x] += t;
        __syncthreads();
    }
    if (gid < n) g_offset[gid] = sh[threadIdx.x] - v;   // exclusive partial
    if (threadIdx.x == 1023) g_blocksums[blockIdx.x] = sh[1023];
}

// K2b: exclusive scan of tile sums (single block)
__global__ void scan_sums_kernel(int nb) {
    __shared__ int sh[MAX_SCAN_BLOCKS];
    int v = (threadIdx.x < nb) ? g_blocksums[threadIdx.x] : 0;
    sh[threadIdx.x] = v;
    __syncthreads();
#pragma unroll
    for (int d = 1; d < MAX_SCAN_BLOCKS; d <<= 1) {
        int t = (threadIdx.x >= d) ? sh[threadIdx.x - d] : 0;
        __syncthreads();
        sh[threadIdx.x] += t;
        __syncthreads();
    }
    if (threadIdx.x < nb) g_blocksums[threadIdx.x] = sh[threadIdx.x] - v;
}

// ---------------------------------------------------------------------------
// K3: bucket fill. Position = atomicAdd on PARTIAL offset + scanned blocksum.
// (After this kernel, g_offset[d] = partial_excl + count, so
//  absolute end = g_offset[d] + g_blocksums[d>>10].)
// ---------------------------------------------------------------------------
__global__ void fill_kernel(const int* __restrict__ src,
                            const int* __restrict__ dst, int e) {
    int i = blockIdx.x * blockDim.x + threadIdx.x;
    if (i >= e) return;
    int d = __ldg(dst + i);
    int old = atomicAdd(&g_offset[d], 1);
    int pos = old + __ldg(g_blocksums + (d >> 10));
    g_sorted_src[pos] = __ldg(src + i);
}

// ---------------------------------------------------------------------------
// K4: gather-accumulate. ONE WARP PER DST NODE.
// Lane owns 2 columns (8B). Per edge: 1 uniform index LDG + 1 LDG.64 +
// 1 add.rn.f32x2. Unroll x4 with 4 independent accumulator chains.
// ---------------------------------------------------------------------------
__global__ void __launch_bounds__(256)
gather_kernel(const float* __restrict__ norm, int n) {
    int node = blockIdx.x * 8 + (threadIdx.x >> 5);
    int lane = threadIdx.x & 31;
    if (node >= n) return;

    int deg = __ldg(g_count + node);
    int end = __ldg(g_offset + node) + __ldg(g_blocksums + (node >> 10));
    int k   = end - deg;

    const unsigned long long* __restrict__ h2 =
        reinterpret_cast<const unsigned long long*>(g_h);

    unsigned long long acc0, acc1, acc2, acc3;
    asm("mov.b64 %0, {%1, %1};" : "=l"(acc0) : "f"(0.0f));
    acc1 = acc0; acc2 = acc0; acc3 = acc0;

    for (; k + 4 <= end; k += 4) {
        int s0 = __ldg(g_sorted_src + k);
        int s1 = __ldg(g_sorted_src + k + 1);
        int s2 = __ldg(g_sorted_src + k + 2);
        int s3 = __ldg(g_sorted_src + k + 3);
        unsigned long long v0 = __ldg(h2 + (size_t)s0 * 32 + lane);
        unsigned long long v1 = __ldg(h2 + (size_t)s1 * 32 + lane);
        unsigned long long v2 = __ldg(h2 + (size_t)s2 * 32 + lane);
        unsigned long long v3 = __ldg(h2 + (size_t)s3 * 32 + lane);
        asm("add.rn.f32x2 %0, %0, %1;" : "+l"(acc0) : "l"(v0));
        asm("add.rn.f32x2 %0, %0, %1;" : "+l"(acc1) : "l"(v1));
        asm("add.rn.f32x2 %0, %0, %1;" : "+l"(acc2) : "l"(v2));
        asm("add.rn.f32x2 %0, %0, %1;" : "+l"(acc3) : "l"(v3));
    }
    for (; k < end; k++) {
        int s = __ldg(g_sorted_src + k);
        unsigned long long v = __ldg(h2 + (size_t)s * 32 + lane);
        asm("add.rn.f32x2 %0, %0, %1;" : "+l"(acc0) : "l"(v));
    }

    asm("add.rn.f32x2 %0, %0, %1;" : "+l"(acc0) : "l"(acc1));
    asm("add.rn.f32x2 %0, %0, %1;" : "+l"(acc2) : "l"(acc3));
    asm("add.rn.f32x2 %0, %0, %1;" : "+l"(acc0) : "l"(acc2));

    float nv = __ldg(norm + node);
    unsigned long long nn;
    asm("mov.b64 %0, {%1, %1};" : "=l"(nn) : "f"(nv));
    asm("mul.rn.f32x2 %0, %0, %1;" : "+l"(acc0) : "l"(nn));

    reinterpret_cast<unsigned long long*>(g_accum)[(size_t)node * 32 + lane] = acc0;
}

// ---------------------------------------------------------------------------
// K5: out = g_accum @ W^T + b   (f32x2 packed FMA, W transposed in shared)
// Block = 256 threads = 64 nodes x 4 col-groups of 16.
// ---------------------------------------------------------------------------
__global__ void __launch_bounds__(256)
linear_kernel(const float* __restrict__ W,
              const float* __restrict__ b,
              float* __restrict__ out, int n) {
    __shared__ float Wt[DIM * DIM];
    __shared__ float bs[DIM];
    int tid = threadIdx.x;
    for (int k = tid; k < DIM * DIM; k += 256) {
        int j = k >> 6, i = k & 63;
        Wt[i * DIM + j] = W[k];
    }
    if (tid < DIM) bs[tid] = b[tid];
    __syncthreads();

    int node = blockIdx.x * 64 + (tid >> 2);
    int jg   = (tid & 3) * 16;
    if (node >= n) return;

    unsigned long long a01, a23, a45, a67, a89, aab, acd, aef;
    asm("mov.b64 %0, {%1, %2};" : "=l"(a01) : "f"(bs[jg + 0]), "f"(bs[jg + 1]));
    asm("mov.b64 %0, {%1, %2};" : "=l"(a23) : "f"(bs[jg + 2]), "f"(bs[jg + 3]));
    asm("mov.b64 %0, {%1, %2};" : "=l"(a45) : "f"(bs[jg + 4]), "f"(bs[jg + 5]));
    asm("mov.b64 %0, {%1, %2};" : "=l"(a67) : "f"(bs[jg + 6]), "f"(bs[jg + 7]));
    asm("mov.b64 %0, {%1, %2};" : "=l"(a89) : "f"(bs[jg + 8]), "f"(bs[jg + 9]));
    asm("mov.b64 %0, {%1, %2};" : "=l"(aab) : "f"(bs[jg + 10]), "f"(bs[jg + 11]));
    asm("mov.b64 %0, {%1, %2};" : "=l"(acd) : "f"(bs[jg + 12]), "f"(bs[jg + 13]));
    asm("mov.b64 %0, {%1, %2};" : "=l"(aef) : "f"(bs[jg + 14]), "f"(bs[jg + 15]));

    const float4* arow = reinterpret_cast<const float4*>(g_accum + (size_t)node * DIM);
#pragma unroll
    for (int i4 = 0; i4 < 16; i4++) {
        float4 a = arow[i4];
        const float av[4] = {a.x, a.y, a.z, a.w};
#pragma unroll
        for (int c = 0; c < 4; c++) {
            int i = i4 * 4 + c;
            unsigned long long aa;
            asm("mov.b64 %0, {%1, %1};" : "=l"(aa) : "f"(av[c]));
            const ulonglong2* wp = reinterpret_cast<const ulonglong2*>(&Wt[i * DIM + jg]);
            ulonglong2 w0 = wp[0], w1 = wp[1];
            asm("fma.rn.f32x2 %0, %1, %2, %0;" : "+l"(a01) : "l"(aa), "l"(w0.x));
            asm("fma.rn.f32x2 %0, %1, %2, %0;" : "+l"(a23) : "l"(aa), "l"(w0.y));
            asm("fma.rn.f32x2 %0, %1, %2, %0;" : "+l"(a45) : "l"(aa), "l"(w1.x));
            asm("fma.rn.f32x2 %0, %1, %2, %0;" : "+l"(a67) : "l"(aa), "l"(w1.y));
            const ulonglong2* wq = reinterpret_cast<const ulonglong2*>(&Wt[i * DIM + jg + 8]);
            ulonglong2 w2 = wq[0], w3 = wq[1];
            asm("fma.rn.f32x2 %0, %1, %2, %0;" : "+l"(a89) : "l"(aa), "l"(w2.x));
            asm("fma.rn.f32x2 %0, %1, %2, %0;" : "+l"(aab) : "l"(aa), "l"(w2.y));
            asm("fma.rn.f32x2 %0, %1, %2, %0;" : "+l"(acd) : "l"(aa), "l"(w3.x));
            asm("fma.rn.f32x2 %0, %1, %2, %0;" : "+l"(aef) : "l"(aa), "l"(w3.y));
        }
    }

    float r[16];
    asm("mov.b64 {%0, %1}, %2;" : "=f"(r[0]), "=f"(r[1]) : "l"(a01));
    asm("mov.b64 {%0, %1}, %2;" : "=f"(r[2]), "=f"(r[3]) : "l"(a23));
    asm("mov.b64 {%0, %1}, %2;" : "=f"(r[4]), "=f"(r[5]) : "l"(a45));
    asm("mov.b64 {%0, %1}, %2;" : "=f"(r[6]), "=f"(r[7]) : "l"(a67));
    asm("mov.b64 {%0, %1}, %2;" : "=f"(r[8]), "=f"(r[9]) : "l"(a89));
    asm("mov.b64 {%0, %1}, %2;" : "=f"(r[10]), "=f"(r[11]) : "l"(aab));
    asm("mov.b64 {%0, %1}, %2;" : "=f"(r[12]), "=f"(r[13]) : "l"(acd));
    asm("mov.b64 {%0, %1}, %2;" : "=f"(r[14]), "=f"(r[15]) : "l"(aef));
    float4* op = reinterpret_cast<float4*>(out + (size_t)node * DIM + jg);
#pragma unroll
    for (int q = 0; q < 4; q++)
        op[q] = make_float4(r[q * 4], r[q * 4 + 1], r[q * 4 + 2], r[q * 4 + 3]);
}

// ---------------------------------------------------------------------------
// Launch. Inputs: 0 feature [N,64] f32, 1 norm [N] f32, 2 src [E] i32,
//                 3 dst [E] i32, 4 W [64,64] f32, 5 b [64] f32. out [N,64] f32.
// ---------------------------------------------------------------------------
extern "C" void kernel_launch(void* const* d_in, const int* in_sizes, int n_in,
                              void* d_out, int out_size) {
    const float* feature = (const float*)d_in[0];
    const float* norm    = (const float*)d_in[1];
    const int*   src     = (const int*)d_in[2];
    const int*   dst     = (const int*)d_in[3];
    const float* W       = (const float*)d_in[4];
    const float* b       = (const float*)d_in[5];
    float*       out     = (float*)d_out;

    int n = in_sizes[1];
    int e = in_sizes[2];

    void* count_ptr = nullptr;
    cudaGetSymbolAddress(&count_ptr, g_count);
    cudaMemsetAsync(count_ptr, 0, (size_t)n * sizeof(int));

    int n_vec4 = n * 16;
    int work = max(n_vec4, e);
    prep_hist_kernel<<<(work + 255) / 256, 256>>>(feature, norm, dst, n_vec4, e);

    int nb = (n + 1023) / 1024;
    scan_block_kernel<<<nb, 1024>>>(n);
    scan_sums_kernel<<<1, MAX_SCAN_BLOCKS>>>(nb);

    fill_kernel<<<(e + 511) / 512, 512>>>(src, dst, e);

    gather_kernel<<<(n + 7) / 8, 256>>>(norm, n);

    linear_kernel<<<(n + 63) / 64, 256>>>(W, b, out, n);
}

// round 5
// speedup vs baseline: 1.3227x; 1.0438x over previous
#include <cuda_runtime.h>
#include <cuda_fp16.h>
#include <cstdint>

#define N_NODES_MAX 100000
#define DIM     64
#define MAX_SCAN_BLOCKS 256

// ---- scratch (allocation-free rule: __device__ globals) ----
__device__ __align__(256) __half g_h16[N_NODES_MAX * DIM];  // fp16 feature*norm_src
__device__ __align__(256) float g_accum[N_NODES_MAX * DIM]; // segment_sum * norm_dst
__device__ int g_count[N_NODES_MAX];         // per-dst degree
__device__ int g_offset[N_NODES_MAX];        // exclusive scan (PARTIAL per 1024-tile)
__device__ int g_sorted_src[2000000];        // src indices grouped by dst
__device__ int g_blocksums[MAX_SCAN_BLOCKS]; // scanned tile sums

// ---------------------------------------------------------------------------
// K1: h16 = fp16(feature * norm) ; histogram of dst (g_count pre-zeroed)
// ---------------------------------------------------------------------------
__global__ void prep_hist_kernel(const float* __restrict__ feature,
                                 const float* __restrict__ norm,
                                 const int* __restrict__ dst,
                                 int n_vec4, int e) {
    int idx = blockIdx.x * blockDim.x + threadIdx.x;
    if (idx < n_vec4) {
        int node = idx >> 4;
        float nv = __ldg(norm + node);
        float4 f = reinterpret_cast<const float4*>(feature)[idx];
        __half2 lo = __floats2half2_rn(f.x * nv, f.y * nv);
        __half2 hi = __floats2half2_rn(f.z * nv, f.w * nv);
        uint2 pack;
        pack.x = *reinterpret_cast<uint32_t*>(&lo);
        pack.y = *reinterpret_cast<uint32_t*>(&hi);
        reinterpret_cast<uint2*>(g_h16)[idx] = pack;
    }
    if (idx < e) atomicAdd(&g_count[__ldg(dst + idx)], 1);
}

// ---------------------------------------------------------------------------
// K2a: per-1024-tile exclusive scan of counts -> g_offset (partial),
//      tile totals -> g_blocksums
// ---------------------------------------------------------------------------
__global__ void scan_block_kernel(int n) {
    __shared__ int sh[1024];
    int gid = blockIdx.x * 1024 + threadIdx.x;
    int v = (gid < n) ? g_count[gid] : 0;
    sh[threadIdx.x] = v;
    __syncthreads();
#pragma unroll
    for (int d = 1; d < 1024; d <<= 1) {
        int t = (threadIdx.x >= d) ? sh[threadIdx.x - d] : 0;
        __syncthreads();
        sh[threadIdx.x] += t;
        __syncthreads();
    }
    if (gid < n) g_offset[gid] = sh[threadIdx.x] - v;   // exclusive partial
    if (threadIdx.x == 1023) g_blocksums[blockIdx.x] = sh[1023];
}

// K2b: exclusive scan of tile sums (single block)
__global__ void scan_sums_kernel(int nb) {
    __shared__ int sh[MAX_SCAN_BLOCKS];
    int v = (threadIdx.x < nb) ? g_blocksums[threadIdx.x] : 0;
    sh[threadIdx.x] = v;
    __syncthreads();
#pragma unroll
    for (int d = 1; d < MAX_SCAN_BLOCKS; d <<= 1) {
        int t = (threadIdx.x >= d) ? sh[threadIdx.x - d] : 0;
        __syncthreads();
        sh[threadIdx.x] += t;
        __syncthreads();
    }
    if (threadIdx.x < nb) g_blocksums[threadIdx.x] = sh[threadIdx.x] - v;
}

// ---------------------------------------------------------------------------
// K3: bucket fill. Position = atomicAdd on PARTIAL offset + scanned blocksum.
// ---------------------------------------------------------------------------
__global__ void fill_kernel(const int* __restrict__ src,
                            const int* __restrict__ dst, int e) {
    int i = blockIdx.x * blockDim.x + threadIdx.x;
    if (i >= e) return;
    int d = __ldg(dst + i);
    int old = atomicAdd(&g_offset[d], 1);
    int pos = old + __ldg(g_blocksums + (d >> 10));
    g_sorted_src[pos] = __ldg(src + i);
}

// ---------------------------------------------------------------------------
// K4: gather-accumulate, fp16 rows. ONE WARP PER DST NODE, TWO EDGES PER
// WARP-INSTRUCTION: lanes 0-15 process even edges, 16-31 odd edges.
// Each lane loads uint2 = 4 halves (8 B); 16 lanes cover the 128 B row.
// Accumulate fp32 in float4; combine halves via shfl.xor(16) at the end.
// ---------------------------------------------------------------------------
__device__ __forceinline__ void acc_h16(float4& a, uint2 v) {
    float2 lo = __half22float2(*reinterpret_cast<__half2*>(&v.x));
    float2 hi = __half22float2(*reinterpret_cast<__half2*>(&v.y));
    a.x += lo.x; a.y += lo.y; a.z += hi.x; a.w += hi.y;
}

__global__ void __launch_bounds__(256)
gather_kernel(const float* __restrict__ norm, int n) {
    int node = blockIdx.x * 8 + (threadIdx.x >> 5);
    int lane = threadIdx.x & 31;
    if (node >= n) return;
    int half = lane >> 4;     // which edge of the pair
    int c16  = lane & 15;     // 8-byte chunk within the 128 B row

    int deg = __ldg(g_count + node);
    int end = __ldg(g_offset + node) + __ldg(g_blocksums + (node >> 10));
    int k   = end - deg;

    const uint2* __restrict__ h2 = reinterpret_cast<const uint2*>(g_h16);

    float4 acc0 = make_float4(0.f, 0.f, 0.f, 0.f);
    float4 acc1 = make_float4(0.f, 0.f, 0.f, 0.f);

    // 8 edges (4 pairs) per iteration
    for (; k + 8 <= end; k += 8) {
        int s0 = __ldg(g_sorted_src + k + 0 + half);
        int s1 = __ldg(g_sorted_src + k + 2 + half);
        int s2 = __ldg(g_sorted_src + k + 4 + half);
        int s3 = __ldg(g_sorted_src + k + 6 + half);
        uint2 v0 = __ldg(h2 + (size_t)s0 * 16 + c16);
        uint2 v1 = __ldg(h2 + (size_t)s1 * 16 + c16);
        uint2 v2 = __ldg(h2 + (size_t)s2 * 16 + c16);
        uint2 v3 = __ldg(h2 + (size_t)s3 * 16 + c16);
        acc_h16(acc0, v0);
        acc_h16(acc1, v1);
        acc_h16(acc0, v2);
        acc_h16(acc1, v3);
    }
    // pairs
    for (; k + 2 <= end; k += 2) {
        int s = __ldg(g_sorted_src + k + half);
        uint2 v = __ldg(h2 + (size_t)s * 16 + c16);
        acc_h16(acc0, v);
    }
    // single leftover edge (half-0 lanes only)
    if (k < end && half == 0) {
        int s = __ldg(g_sorted_src + k);
        uint2 v = __ldg(h2 + (size_t)s * 16 + c16);
        acc_h16(acc0, v);
    }

    acc0.x += acc1.x; acc0.y += acc1.y; acc0.z += acc1.z; acc0.w += acc1.w;
    acc0.x += __shfl_xor_sync(0xffffffffu, acc0.x, 16);
    acc0.y += __shfl_xor_sync(0xffffffffu, acc0.y, 16);
    acc0.z += __shfl_xor_sync(0xffffffffu, acc0.z, 16);
    acc0.w += __shfl_xor_sync(0xffffffffu, acc0.w, 16);

    if (half == 0) {
        float nv = __ldg(norm + node);
        acc0.x *= nv; acc0.y *= nv; acc0.z *= nv; acc0.w *= nv;
        reinterpret_cast<float4*>(g_accum + (size_t)node * DIM)[c16] = acc0;
    }
}

// ---------------------------------------------------------------------------
// K5: out = g_accum @ W^T + b   (f32x2 packed FMA, W transposed in shared)
// Block = 256 threads = 64 nodes x 4 col-groups of 16.
// ---------------------------------------------------------------------------
__global__ void __launch_bounds__(256)
linear_kernel(const float* __restrict__ W,
              const float* __restrict__ b,
              float* __restrict__ out, int n) {
    __shared__ float Wt[DIM * DIM];
    __shared__ float bs[DIM];
    int tid = threadIdx.x;
    for (int k = tid; k < DIM * DIM; k += 256) {
        int j = k >> 6, i = k & 63;
        Wt[i * DIM + j] = W[k];
    }
    if (tid < DIM) bs[tid] = b[tid];
    __syncthreads();

    int node = blockIdx.x * 64 + (tid >> 2);
    int jg   = (tid & 3) * 16;
    if (node >= n) return;

    unsigned long long a01, a23, a45, a67, a89, aab, acd, aef;
    asm("mov.b64 %0, {%1, %2};" : "=l"(a01) : "f"(bs[jg + 0]), "f"(bs[jg + 1]));
    asm("mov.b64 %0, {%1, %2};" : "=l"(a23) : "f"(bs[jg + 2]), "f"(bs[jg + 3]));
    asm("mov.b64 %0, {%1, %2};" : "=l"(a45) : "f"(bs[jg + 4]), "f"(bs[jg + 5]));
    asm("mov.b64 %0, {%1, %2};" : "=l"(a67) : "f"(bs[jg + 6]), "f"(bs[jg + 7]));
    asm("mov.b64 %0, {%1, %2};" : "=l"(a89) : "f"(bs[jg + 8]), "f"(bs[jg + 9]));
    asm("mov.b64 %0, {%1, %2};" : "=l"(aab) : "f"(bs[jg + 10]), "f"(bs[jg + 11]));
    asm("mov.b64 %0, {%1, %2};" : "=l"(acd) : "f"(bs[jg + 12]), "f"(bs[jg + 13]));
    asm("mov.b64 %0, {%1, %2};" : "=l"(aef) : "f"(bs[jg + 14]), "f"(bs[jg + 15]));

    const float4* arow = reinterpret_cast<const float4*>(g_accum + (size_t)node * DIM);
#pragma unroll
    for (int i4 = 0; i4 < 16; i4++) {
        float4 a = arow[i4];
        const float av[4] = {a.x, a.y, a.z, a.w};
#pragma unroll
        for (int c = 0; c < 4; c++) {
            int i = i4 * 4 + c;
            unsigned long long aa;
            asm("mov.b64 %0, {%1, %1};" : "=l"(aa) : "f"(av[c]));
            const ulonglong2* wp = reinterpret_cast<const ulonglong2*>(&Wt[i * DIM + jg]);
            ulonglong2 w0 = wp[0], w1 = wp[1];
            asm("fma.rn.f32x2 %0, %1, %2, %0;" : "+l"(a01) : "l"(aa), "l"(w0.x));
            asm("fma.rn.f32x2 %0, %1, %2, %0;" : "+l"(a23) : "l"(aa), "l"(w0.y));
            asm("fma.rn.f32x2 %0, %1, %2, %0;" : "+l"(a45) : "l"(aa), "l"(w1.x));
            asm("fma.rn.f32x2 %0, %1, %2, %0;" : "+l"(a67) : "l"(aa), "l"(w1.y));
            const ulonglong2* wq = reinterpret_cast<const ulonglong2*>(&Wt[i * DIM + jg + 8]);
            ulonglong2 w2 = wq[0], w3 = wq[1];
            asm("fma.rn.f32x2 %0, %1, %2, %0;" : "+l"(a89) : "l"(aa), "l"(w2.x));
            asm("fma.rn.f32x2 %0, %1, %2, %0;" : "+l"(aab) : "l"(aa), "l"(w2.y));
            asm("fma.rn.f32x2 %0, %1, %2, %0;" : "+l"(acd) : "l"(aa), "l"(w3.x));
            asm("fma.rn.f32x2 %0, %1, %2, %0;" : "+l"(aef) : "l"(aa), "l"(w3.y));
        }
    }

    float r[16];
    asm("mov.b64 {%0, %1}, %2;" : "=f"(r[0]), "=f"(r[1]) : "l"(a01));
    asm("mov.b64 {%0, %1}, %2;" : "=f"(r[2]), "=f"(r[3]) : "l"(a23));
    asm("mov.b64 {%0, %1}, %2;" : "=f"(r[4]), "=f"(r[5]) : "l"(a45));
    asm("mov.b64 {%0, %1}, %2;" : "=f"(r[6]), "=f"(r[7]) : "l"(a67));
    asm("mov.b64 {%0, %1}, %2;" : "=f"(r[8]), "=f"(r[9]) : "l"(a89));
    asm("mov.b64 {%0, %1}, %2;" : "=f"(r[10]), "=f"(r[11]) : "l"(aab));
    asm("mov.b64 {%0, %1}, %2;" : "=f"(r[12]), "=f"(r[13]) : "l"(acd));
    asm("mov.b64 {%0, %1}, %2;" : "=f"(r[14]), "=f"(r[15]) : "l"(aef));
    float4* op = reinterpret_cast<float4*>(out + (size_t)node * DIM + jg);
#pragma unroll
    for (int q = 0; q < 4; q++)
        op[q] = make_float4(r[q * 4], r[q * 4 + 1], r[q * 4 + 2], r[q * 4 + 3]);
}

// ---------------------------------------------------------------------------
// Launch. Inputs: 0 feature [N,64] f32, 1 norm [N] f32, 2 src [E] i32,
//                 3 dst [E] i32, 4 W [64,64] f32, 5 b [64] f32. out [N,64] f32.
// ---------------------------------------------------------------------------
extern "C" void kernel_launch(void* const* d_in, const int* in_sizes, int n_in,
                              void* d_out, int out_size) {
    const float* feature = (const float*)d_in[0];
    const float* norm    = (const float*)d_in[1];
    const int*   src     = (const int*)d_in[2];
    const int*   dst     = (const int*)d_in[3];
    const float* W       = (const float*)d_in[4];
    const float* b       = (const float*)d_in[5];
    float*       out     = (float*)d_out;

    int n = in_sizes[1];
    int e = in_sizes[2];

    void* count_ptr = nullptr;
    cudaGetSymbolAddress(&count_ptr, g_count);
    cudaMemsetAsync(count_ptr, 0, (size_t)n * sizeof(int));

    int n_vec4 = n * 16;
    int work = max(n_vec4, e);
    prep_hist_kernel<<<(work + 255) / 256, 256>>>(feature, norm, dst, n_vec4, e);

    int nb = (n + 1023) / 1024;
    scan_block_kernel<<<nb, 1024>>>(n);
    scan_sums_kernel<<<1, MAX_SCAN_BLOCKS>>>(nb);

    fill_kernel<<<(e + 511) / 512, 512>>>(src, dst, e);

    gather_kernel<<<(n + 7) / 8, 256>>>(norm, n);

    linear_kernel<<<(n + 63) / 64, 256>>>(W, b, out, n);
}